// round 6
// baseline (speedup 1.0000x reference)
#include <cuda_runtime.h>
#include <cstdint>

#define NN 100000
#define EE 1600000
#define DD 128
#define NG 64

// ---------------- scratch (static device globals; no allocation) ----------------
__device__ int      g_ei64, g_b64;
__device__ int      g_degi[NN];
__device__ int      g_start[NN];
__device__ int      g_cursor[NN];
__device__ int      g_bsum[512];
__device__ int      g_cnti[NG];
__device__ int      g_csr[EE];
__device__ float    g_winv[NN];
__device__ float    g_cinv[NG];
__device__ unsigned g_pb[(size_t)NN * 64];   // P in packed bf16x2 (row = 64 uints)
__device__ float    g_q[(size_t)NN * DD];    // Q in fp32
__device__ float    g_h1[(size_t)NN * DD];
__device__ float    g_z[(size_t)NN * 4];
__device__ unsigned g_wsp[4][2][64][DD];     // pre-split weights: [matrix][plane][k/2][n] bf16x2
__device__ float    g_Wcl[DD * 2];
__device__ float    g_Wcr[DD * 2];
__device__ float    g_cb[2];
__device__ float    g_acc[NG * 2];

// ---------------- helpers ----------------
__device__ __forceinline__ unsigned pack_bf2(float lo, float hi) {
    unsigned r;
    asm("cvt.rn.bf16x2.f32 %0, %1, %2;" : "=r"(r) : "f"(hi), "f"(lo));
    return r;
}
// split (x0,x1) -> plane0 (hi bf16 pair), plane1 (residual bf16 pair)
__device__ __forceinline__ void split2(float x0, float x1, unsigned& p0, unsigned& p1) {
    p0 = pack_bf2(x0, x1);
    float h0 = __uint_as_float(p0 << 16);
    float h1 = __uint_as_float(p0 & 0xFFFF0000u);
    p1 = pack_bf2(x0 - h0, x1 - h1);
}

__device__ __forceinline__ void mma_bf16(float* d, const unsigned* a, const unsigned* b) {
    asm volatile(
        "mma.sync.aligned.m16n8k16.row.col.f32.bf16.bf16.f32 "
        "{%0,%1,%2,%3}, {%4,%5,%6,%7}, {%8,%9}, {%0,%1,%2,%3};"
        : "+f"(d[0]), "+f"(d[1]), "+f"(d[2]), "+f"(d[3])
        : "r"(a[0]), "r"(a[1]), "r"(a[2]), "r"(a[3]), "r"(b[0]), "r"(b[1]));
}

// ---------------- dtype detection (int32 vs int64) ----------------
__global__ void detect_kernel(const void* ei, const void* batch) {
    const long long* p = (const long long*)ei;
    bool e64 = true;
    #pragma unroll
    for (int i = 0; i < 16; i++) {
        long long v = p[(size_t)i * 99991];
        if (v < 0 || v >= NN) e64 = false;
    }
    g_ei64 = e64 ? 1 : 0;
    const long long* q = (const long long*)batch;  // sorted: sample near the end
    bool b64 = true;
    #pragma unroll
    for (int i = 0; i < 8; i++) {
        long long v = q[NN / 2 - 1 - i * 37];
        if (v < 0 || v >= NG) b64 = false;
    }
    g_b64 = b64 ? 1 : 0;
}

__device__ __forceinline__ int ld_ei(const void* p, long long i) {
    return g_ei64 ? (int)((const long long*)p)[i] : ((const int*)p)[i];
}
__device__ __forceinline__ int ld_b(const void* p, long long i) {
    return g_b64 ? (int)((const long long*)p)[i] : ((const int*)p)[i];
}

// ---------------- small init ----------------
__global__ void zero_small_kernel() {
    int i = blockIdx.x * blockDim.x + threadIdx.x;
    if (i < NN) g_degi[i] = 0;
    if (i < NG) g_cnti[i] = 0;
    if (i < NG * 2) g_acc[i] = 0.0f;
}

// ---------------- pre-split W matrices into bf16 hi/lo planes ----------------
__global__ void __launch_bounds__(256) presplit_kernel(const float* __restrict__ Wl1,
                                                       const float* __restrict__ Wr1,
                                                       const float* __restrict__ Wl2,
                                                       const float* __restrict__ Wr2) {
    int idx = blockIdx.x * 256 + threadIdx.x;   // 0..32767
    int mat = idx >> 13;
    int rem = idx & 8191;
    int k2 = rem >> 7;
    int n = rem & 127;
    const float* W = (mat == 0) ? Wl1 : (mat == 1) ? Wr1 : (mat == 2) ? Wl2 : Wr2;
    float w0 = W[(2 * k2) * DD + n];
    float w1 = W[(2 * k2 + 1) * DD + n];
    unsigned p0, p1;
    split2(w0, w1, p0, p1);
    g_wsp[mat][0][k2][n] = p0;
    g_wsp[mat][1][k2][n] = p1;
}

// ---------------- bf16x3 GEMM: Pbf16 = X@W[matL], Q = X@W[matR] ----------------
// 256 threads (8 warps, 4x2 warpgrid, warp tile 32x64). Full A split cached in smem.
extern __shared__ unsigned sm_dyn[];
#define GEMM_SMEM ((2 * 64 * 136 + 2 * 8 * 136) * 4)

__global__ void __launch_bounds__(256, 2) gemm_bf16x3_kernel(const float* __restrict__ X,
                                                             int matL, int matR,
                                                             unsigned* __restrict__ Pout,
                                                             float* __restrict__ Qout) {
    unsigned* As0 = sm_dyn;                    // [64][136]
    unsigned* As1 = sm_dyn + 64 * 136;
    unsigned* Bs0 = sm_dyn + 2 * 64 * 136;     // [8][136]
    unsigned* Bs1 = Bs0 + 8 * 136;

    int tid = threadIdx.x;
    int warp = tid >> 5, lane = tid & 31;
    int g = lane >> 2, t = lane & 3;
    int wm = (warp >> 1) * 32, wn = (warp & 1) * 64;
    int row0 = blockIdx.x * 128;

    // ---- load & split the full 128x128 A tile ----
    #pragma unroll
    for (int i = 0; i < 16; i++) {
        int slot = tid + 256 * i;              // 0..4095
        int m = slot >> 5;                     // 0..127
        int k4 = (slot & 31) * 4;              // 0..124
        int r = row0 + m;
        float4 av = (r < NN) ? *(const float4*)(X + (size_t)r * DD + k4)
                             : make_float4(0.f, 0.f, 0.f, 0.f);
        unsigned p0, p1, q0, q1;
        split2(av.x, av.y, p0, p1);
        split2(av.z, av.w, q0, q1);
        int k2 = k4 >> 1;
        As0[k2 * 136 + m] = p0;  As0[(k2 + 1) * 136 + m] = q0;
        As1[k2 * 136 + m] = p1;  As1[(k2 + 1) * 136 + m] = q1;
    }

    #pragma unroll
    for (int phase = 0; phase < 2; phase++) {
        const unsigned* Wsp = &g_wsp[phase ? matR : matL][0][0][0];
        float acc[2][8][4];
        #pragma unroll
        for (int a = 0; a < 2; a++)
            #pragma unroll
            for (int b = 0; b < 8; b++)
                #pragma unroll
                for (int c = 0; c < 4; c++) acc[a][b][c] = 0.0f;

        for (int ko2 = 0; ko2 < 64; ko2 += 8) {
            __syncthreads();   // prior Bs consumed (and A-split visible on first pass)
            #pragma unroll
            for (int i = 0; i < 2; i++) {
                int slot = tid + 256 * i;       // 0..511 uint4 slots
                int p = slot >> 8;
                int rem = slot & 255;
                int k2l = rem >> 5;
                int n4 = (rem & 31) * 4;
                uint4 v = *(const uint4*)(Wsp + ((size_t)p * 64 + ko2 + k2l) * DD + n4);
                *(uint4*)((p ? Bs1 : Bs0) + k2l * 136 + n4) = v;
            }
            __syncthreads();

            unsigned a0f[2][4], a1f[2][4];
            #pragma unroll
            for (int mt = 0; mt < 2; mt++) {
                int m = wm + mt * 16 + g;
                a0f[mt][0] = As0[(ko2 + t) * 136 + m];
                a0f[mt][1] = As0[(ko2 + t) * 136 + m + 8];
                a0f[mt][2] = As0[(ko2 + t + 4) * 136 + m];
                a0f[mt][3] = As0[(ko2 + t + 4) * 136 + m + 8];
                a1f[mt][0] = As1[(ko2 + t) * 136 + m];
                a1f[mt][1] = As1[(ko2 + t) * 136 + m + 8];
                a1f[mt][2] = As1[(ko2 + t + 4) * 136 + m];
                a1f[mt][3] = As1[(ko2 + t + 4) * 136 + m + 8];
            }
            #pragma unroll
            for (int nt = 0; nt < 8; nt++) {
                int n = wn + nt * 8 + g;
                unsigned b0[2], b1[2];
                b0[0] = Bs0[t * 136 + n];
                b0[1] = Bs0[(t + 4) * 136 + n];
                b1[0] = Bs1[t * 136 + n];
                b1[1] = Bs1[(t + 4) * 136 + n];
                #pragma unroll
                for (int mt = 0; mt < 2; mt++) {
                    mma_bf16(acc[mt][nt], a0f[mt], b0);
                    mma_bf16(acc[mt][nt], a0f[mt], b1);
                    mma_bf16(acc[mt][nt], a1f[mt], b0);
                }
            }
        }
        // ---- epilogue ----
        if (phase == 0) {
            #pragma unroll
            for (int mt = 0; mt < 2; mt++) {
                #pragma unroll
                for (int nt = 0; nt < 8; nt++) {
                    int r = row0 + wm + mt * 16 + g;
                    int c = wn + nt * 8 + 2 * t;
                    if (r < NN) Pout[(size_t)r * 64 + (c >> 1)] = pack_bf2(acc[mt][nt][0], acc[mt][nt][1]);
                    if (r + 8 < NN) Pout[(size_t)(r + 8) * 64 + (c >> 1)] = pack_bf2(acc[mt][nt][2], acc[mt][nt][3]);
                }
            }
        } else {
            #pragma unroll
            for (int mt = 0; mt < 2; mt++) {
                #pragma unroll
                for (int nt = 0; nt < 8; nt++) {
                    int r = row0 + wm + mt * 16 + g;
                    int c = wn + nt * 8 + 2 * t;
                    if (r < NN)
                        *(float2*)(Qout + (size_t)r * DD + c) = make_float2(acc[mt][nt][0], acc[mt][nt][1]);
                    if (r + 8 < NN)
                        *(float2*)(Qout + (size_t)(r + 8) * DD + c) = make_float2(acc[mt][nt][2], acc[mt][nt][3]);
                }
            }
        }
    }
}

// ---------------- degree / counts / scan / place ----------------
__global__ void deg_kernel(const void* __restrict__ ei) {
    int e = blockIdx.x * blockDim.x + threadIdx.x;
    if (e >= EE) return;
    unsigned d = (unsigned)ld_ei(ei, (long long)EE + e);
    if (d >= NN) return;
    atomicAdd(&g_degi[d], 1);
}

__global__ void __launch_bounds__(256) cnt_hist_kernel(const void* __restrict__ batch) {
    __shared__ int sh[NG];
    if (threadIdx.x < NG) sh[threadIdx.x] = 0;
    __syncthreads();
    int i = blockIdx.x * blockDim.x + threadIdx.x;
    if (i < NN) {
        unsigned g = (unsigned)ld_b(batch, i);
        if (g < NG) atomicAdd(&sh[g], 1);
    }
    __syncthreads();
    if (threadIdx.x < NG && sh[threadIdx.x] != 0) atomicAdd(&g_cnti[threadIdx.x], sh[threadIdx.x]);
}

__global__ void __launch_bounds__(256) scan1_kernel() {
    __shared__ int sdata[256];
    int t = threadIdx.x;
    int i = blockIdx.x * 256 + t;
    int v = (i < NN) ? g_degi[i] : 0;
    sdata[t] = v;
    __syncthreads();
    #pragma unroll
    for (int off = 1; off < 256; off <<= 1) {
        int x = (t >= off) ? sdata[t - off] : 0;
        __syncthreads();
        sdata[t] += x;
        __syncthreads();
    }
    int incl = sdata[t];
    if (i < NN) g_start[i] = incl - v;
    if (t == 255) g_bsum[blockIdx.x] = incl;
}

__global__ void __launch_bounds__(512) scan2_kernel(int nb) {
    __shared__ int sdata[512];
    int t = threadIdx.x;
    int v = (t < nb) ? g_bsum[t] : 0;
    sdata[t] = v;
    __syncthreads();
    #pragma unroll
    for (int off = 1; off < 512; off <<= 1) {
        int x = (t >= off) ? sdata[t - off] : 0;
        __syncthreads();
        sdata[t] += x;
        __syncthreads();
    }
    if (t < nb) g_bsum[t] = sdata[t] - v;   // exclusive
    if (t < NG) g_cinv[t] = 1.0f / fmaxf((float)g_cnti[t], 1.0f);
}

__global__ void __launch_bounds__(256) scan3_kernel() {
    int i = blockIdx.x * 256 + threadIdx.x;
    if (i >= NN) return;
    int s = g_start[i] + g_bsum[i >> 8];
    g_start[i] = s;
    g_cursor[i] = s;
    g_winv[i] = 1.0f / fmaxf((float)g_degi[i], 1.0f);
}

__global__ void __launch_bounds__(256) place_kernel(const void* __restrict__ ei) {
    int e = blockIdx.x * blockDim.x + threadIdx.x;
    if (e >= EE) return;
    unsigned s = (unsigned)ld_ei(ei, e);
    unsigned d = (unsigned)ld_ei(ei, (long long)EE + e);
    if (s >= NN || d >= NN) return;
    int pos = atomicAdd(&g_cursor[d], 1);
    g_csr[pos] = (int)s;
}

// ---------------- CSR gather (bf16 P) + epilogue: H = relu(winv*sum(P[nbr]) + Q + b) ----------------
__device__ __forceinline__ void acc_bf2(float4& acc, uint2 v) {
    acc.x += __uint_as_float(v.x << 16);
    acc.y += __uint_as_float(v.x & 0xFFFF0000u);
    acc.z += __uint_as_float(v.y << 16);
    acc.w += __uint_as_float(v.y & 0xFFFF0000u);
}

__global__ void __launch_bounds__(256) gather_kernel(const unsigned* __restrict__ P,
                                                     const float* __restrict__ Q,
                                                     const float* __restrict__ bias,
                                                     float* __restrict__ H) {
    int node = blockIdx.x * 8 + (threadIdx.x >> 5);
    int lane = threadIdx.x & 31;
    int s = g_start[node];
    int d = g_degi[node];
    float4 acc = make_float4(0.f, 0.f, 0.f, 0.f);
    for (int j = 0; j < d; j++) {
        int src = g_csr[s + j];
        uint2 v = ((const uint2*)(P + (size_t)src * 64))[lane];
        acc_bf2(acc, v);
    }
    float w = g_winv[node];
    float4 q = ((const float4*)(Q + (size_t)node * DD))[lane];
    float4 b = ((const float4*)bias)[lane];
    float4 o;
    o.x = fmaxf(acc.x * w + q.x + b.x, 0.0f);
    o.y = fmaxf(acc.y * w + q.y + b.y, 0.0f);
    o.z = fmaxf(acc.z * w + q.z + b.z, 0.0f);
    o.w = fmaxf(acc.w * w + q.w + b.w, 0.0f);
    ((float4*)(H + (size_t)node * DD))[lane] = o;
}

// ---------------- layer-2 gather fused with layer-3 projection -> z ----------------
__global__ void __launch_bounds__(256) gather2z_kernel(const unsigned* __restrict__ P,
                                                       const float* __restrict__ Q,
                                                       const float* __restrict__ bias) {
    int node = blockIdx.x * 8 + (threadIdx.x >> 5);
    int lane = threadIdx.x & 31;
    int s = g_start[node];
    int d = g_degi[node];
    float4 acc = make_float4(0.f, 0.f, 0.f, 0.f);
    for (int j = 0; j < d; j++) {
        int src = g_csr[s + j];
        uint2 v = ((const uint2*)(P + (size_t)src * 64))[lane];
        acc_bf2(acc, v);
    }
    float w = g_winv[node];
    float4 q = ((const float4*)(Q + (size_t)node * DD))[lane];
    float4 b = ((const float4*)bias)[lane];
    float hv[4];
    hv[0] = fmaxf(acc.x * w + q.x + b.x, 0.0f);
    hv[1] = fmaxf(acc.y * w + q.y + b.y, 0.0f);
    hv[2] = fmaxf(acc.z * w + q.z + b.z, 0.0f);
    hv[3] = fmaxf(acc.w * w + q.w + b.w, 0.0f);
    float s0 = 0.f, s1 = 0.f, s2 = 0.f, s3 = 0.f;
    #pragma unroll
    for (int j = 0; j < 4; j++) {
        int k = lane * 4 + j;
        s0 += hv[j] * g_Wcl[k * 2 + 0];
        s1 += hv[j] * g_Wcl[k * 2 + 1];
        s2 += hv[j] * g_Wcr[k * 2 + 0];
        s3 += hv[j] * g_Wcr[k * 2 + 1];
    }
    #pragma unroll
    for (int o = 16; o > 0; o >>= 1) {
        s0 += __shfl_down_sync(0xFFFFFFFFu, s0, o);
        s1 += __shfl_down_sync(0xFFFFFFFFu, s1, o);
        s2 += __shfl_down_sync(0xFFFFFFFFu, s2, o);
        s3 += __shfl_down_sync(0xFFFFFFFFu, s3, o);
    }
    if (lane == 0) ((float4*)g_z)[node] = make_float4(s0, s1, s2, s3);
}

// ---------------- layer-3 fold ----------------
__global__ void foldW_kernel(const float* __restrict__ Wl3, const float* __restrict__ Wr3,
                             const float* __restrict__ bl3, const float* __restrict__ Wlin,
                             const float* __restrict__ blin) {
    int k = threadIdx.x;
    float a0 = 0.f, a1 = 0.f, b0 = 0.f, b1 = 0.f;
    for (int m = 0; m < DD; m++) {
        float wl = Wl3[k * DD + m], wr = Wr3[k * DD + m];
        float l0 = Wlin[m * 2 + 0], l1 = Wlin[m * 2 + 1];
        a0 += wl * l0; a1 += wl * l1;
        b0 += wr * l0; b1 += wr * l1;
    }
    g_Wcl[k * 2 + 0] = a0; g_Wcl[k * 2 + 1] = a1;
    g_Wcr[k * 2 + 0] = b0; g_Wcr[k * 2 + 1] = b1;
    if (k < 2) {
        float cv = blin[k];
        for (int m = 0; m < DD; m++) cv += bl3[m] * Wlin[m * 2 + k];
        g_cb[k] = cv;
    }
}

// ---------------- layer-3 pooled reduction ----------------
__global__ void __launch_bounds__(256) pool3_kernel(const void* __restrict__ batch) {
    __shared__ float sh[NG * 2];
    for (int i = threadIdx.x; i < NG * 2; i += blockDim.x) sh[i] = 0.0f;
    __syncthreads();
    int n = blockIdx.x * 256 + threadIdx.x;
    if (n < NN) {
        int s = g_start[n], d = g_degi[n];
        float s0 = 0.f, s1 = 0.f;
        for (int j = 0; j < d; j++) {
            int src = g_csr[s + j];
            float2 zl = *(const float2*)(g_z + (size_t)src * 4);
            s0 += zl.x; s1 += zl.y;
        }
        float w = g_winv[n];
        unsigned gg = (unsigned)ld_b(batch, n);
        if (gg < NG) {
            float ci = g_cinv[gg];
            float2 zr = *(const float2*)(g_z + (size_t)n * 4 + 2);
            atomicAdd(&sh[gg * 2 + 0], ci * (w * s0 + zr.x));
            atomicAdd(&sh[gg * 2 + 1], ci * (w * s1 + zr.y));
        }
    }
    __syncthreads();
    for (int i = threadIdx.x; i < NG * 2; i += blockDim.x)
        if (sh[i] != 0.0f) atomicAdd(&g_acc[i], sh[i]);
}

__global__ void finalize_kernel(float* __restrict__ out) {
    int t = threadIdx.x;
    if (t < NG * 2) out[t] = g_acc[t] + g_cb[t & 1];
}

// ---------------- host launcher ----------------
extern "C" void kernel_launch(void* const* d_in, const int* in_sizes, int n_in,
                              void* d_out, int out_size) {
    const float* x = (const float*)d_in[0];
    const void* ei = d_in[1];
    const void* batch = d_in[2];
    const float* Wl1 = (const float*)d_in[3];
    const float* bl1 = (const float*)d_in[4];
    const float* Wr1 = (const float*)d_in[5];
    const float* Wl2 = (const float*)d_in[6];
    const float* bl2 = (const float*)d_in[7];
    const float* Wr2 = (const float*)d_in[8];
    const float* Wl3 = (const float*)d_in[9];
    const float* bl3 = (const float*)d_in[10];
    const float* Wr3 = (const float*)d_in[11];
    const float* Wlin = (const float*)d_in[12];
    const float* blin = (const float*)d_in[13];
    float* out = (float*)d_out;

    // __device__ symbols are not host pointers: resolve real addresses.
    unsigned* pp = nullptr;
    float *qp = nullptr, *h1p = nullptr;
    cudaGetSymbolAddress((void**)&pp, g_pb);
    cudaGetSymbolAddress((void**)&qp, g_q);
    cudaGetSymbolAddress((void**)&h1p, g_h1);

    cudaFuncSetAttribute(gemm_bf16x3_kernel,
                         cudaFuncAttributeMaxDynamicSharedMemorySize, GEMM_SMEM);

    const int nb = (NN + 255) / 256;           // 391
    const int gemm_blocks = (NN + 127) / 128;  // 782

    detect_kernel<<<1, 1>>>(ei, batch);
    zero_small_kernel<<<nb, 256>>>();
    presplit_kernel<<<128, 256>>>(Wl1, Wr1, Wl2, Wr2);
    gemm_bf16x3_kernel<<<gemm_blocks, 256, GEMM_SMEM>>>(x, 0, 1, pp, qp);   // profile slot
    deg_kernel<<<(EE + 255) / 256, 256>>>(ei);
    cnt_hist_kernel<<<nb, 256>>>(batch);
    scan1_kernel<<<nb, 256>>>();
    scan2_kernel<<<1, 512>>>(nb);
    scan3_kernel<<<nb, 256>>>();
    place_kernel<<<(EE + 255) / 256, 256>>>(ei);

    gather_kernel<<<NN / 8, 256>>>(pp, qp, bl1, h1p);
    gemm_bf16x3_kernel<<<gemm_blocks, 256, GEMM_SMEM>>>(h1p, 2, 3, pp, qp);
    foldW_kernel<<<1, 128>>>(Wl3, Wr3, bl3, Wlin, blin);
    gather2z_kernel<<<NN / 8, 256>>>(pp, qp, bl2);
    pool3_kernel<<<nb, 256>>>(batch);
    finalize_kernel<<<1, 128>>>(out);
}

// round 7
// speedup vs baseline: 1.0879x; 1.0879x over previous
#include <cuda_runtime.h>
#include <cstdint>

#define NN 100000
#define EE 1600000
#define DD 128
#define NG 64

// ---------------- scratch (static device globals; no allocation) ----------------
__device__ int      g_ei64, g_b64;
__device__ int      g_degi[NN];
__device__ int      g_start[NN];
__device__ int      g_cursor[NN];
__device__ int      g_bsum[512];
__device__ int      g_cnti[NG];
__device__ int      g_csr[EE];
__device__ float    g_winv[NN];
__device__ float    g_cinv[NG];
__device__ unsigned g_pb[(size_t)NN * 64];   // P in packed bf16x2 (row = 64 uints)
__device__ float    g_q[(size_t)NN * DD];    // Q in fp32
__device__ float    g_h1[(size_t)NN * DD];
__device__ float    g_z[(size_t)NN * 4];
__device__ unsigned g_wspT[4][2][DD][64];    // pre-split W, TRANSPOSED: [mat][plane][n][k2] bf16x2
__device__ float    g_Wcl[DD * 2];
__device__ float    g_Wcr[DD * 2];
__device__ float    g_cb[2];
__device__ float    g_acc[NG * 2];

// ---------------- helpers ----------------
__device__ __forceinline__ unsigned pack_bf2(float lo, float hi) {
    unsigned r;
    asm("cvt.rn.bf16x2.f32 %0, %1, %2;" : "=r"(r) : "f"(hi), "f"(lo));
    return r;
}
__device__ __forceinline__ void split2(float x0, float x1, unsigned& p0, unsigned& p1) {
    p0 = pack_bf2(x0, x1);
    float h0 = __uint_as_float(p0 << 16);
    float h1 = __uint_as_float(p0 & 0xFFFF0000u);
    p1 = pack_bf2(x0 - h0, x1 - h1);
}
__device__ __forceinline__ void mma_bf16(float* d, const unsigned* a, const unsigned* b) {
    asm volatile(
        "mma.sync.aligned.m16n8k16.row.col.f32.bf16.bf16.f32 "
        "{%0,%1,%2,%3}, {%4,%5,%6,%7}, {%8,%9}, {%0,%1,%2,%3};"
        : "+f"(d[0]), "+f"(d[1]), "+f"(d[2]), "+f"(d[3])
        : "r"(a[0]), "r"(a[1]), "r"(a[2]), "r"(a[3]), "r"(b[0]), "r"(b[1]));
}
__device__ __forceinline__ void ldsm_x4(unsigned& r0, unsigned& r1, unsigned& r2, unsigned& r3,
                                        unsigned saddr) {
    asm volatile("ldmatrix.sync.aligned.m8n8.x4.shared.b16 {%0,%1,%2,%3}, [%4];"
                 : "=r"(r0), "=r"(r1), "=r"(r2), "=r"(r3) : "r"(saddr));
}

// ---------------- dtype detection (int32 vs int64) ----------------
__global__ void detect_kernel(const void* ei, const void* batch) {
    const long long* p = (const long long*)ei;
    bool e64 = true;
    #pragma unroll
    for (int i = 0; i < 16; i++) {
        long long v = p[(size_t)i * 99991];
        if (v < 0 || v >= NN) e64 = false;
    }
    g_ei64 = e64 ? 1 : 0;
    const long long* q = (const long long*)batch;
    bool b64 = true;
    #pragma unroll
    for (int i = 0; i < 8; i++) {
        long long v = q[NN / 2 - 1 - i * 37];
        if (v < 0 || v >= NG) b64 = false;
    }
    g_b64 = b64 ? 1 : 0;
}
__device__ __forceinline__ int ld_ei(const void* p, long long i) {
    return g_ei64 ? (int)((const long long*)p)[i] : ((const int*)p)[i];
}
__device__ __forceinline__ int ld_b(const void* p, long long i) {
    return g_b64 ? (int)((const long long*)p)[i] : ((const int*)p)[i];
}

// ---------------- small init ----------------
__global__ void zero_small_kernel() {
    int i = blockIdx.x * blockDim.x + threadIdx.x;
    if (i < NN) g_degi[i] = 0;
    if (i < NG) g_cnti[i] = 0;
    if (i < NG * 2) g_acc[i] = 0.0f;
}

// ---------------- pre-split W into bf16 hi/lo planes, TRANSPOSED [n][k2] ----------------
__global__ void __launch_bounds__(256) presplit_kernel(const float* __restrict__ Wl1,
                                                       const float* __restrict__ Wr1,
                                                       const float* __restrict__ Wl2,
                                                       const float* __restrict__ Wr2) {
    int idx = blockIdx.x * 256 + threadIdx.x;   // 0..32767
    int mat = idx >> 13;
    int rem = idx & 8191;
    int k2 = rem >> 7;
    int n = rem & 127;
    const float* W = (mat == 0) ? Wl1 : (mat == 1) ? Wr1 : (mat == 2) ? Wl2 : Wr2;
    float w0 = W[(2 * k2) * DD + n];
    float w1 = W[(2 * k2 + 1) * DD + n];
    unsigned p0, p1;
    split2(w0, w1, p0, p1);
    g_wspT[mat][0][n][k2] = p0;
    g_wspT[mat][1][n][k2] = p1;
}

// ---------------- bf16x3 GEMM via ldmatrix ----------------
// 128 threads, 4 warps (2x2 grid of 64x64 warp tiles), block tile 128x128.
// A split resident in smem, row-major, 272B row stride (conflict-free LDSM).
// B chunk in smem, n-major, 48B row stride (conflict-free LDSM).
extern __shared__ unsigned sm_dyn[];
#define AS_STR 68            // uints per A row (64 data + 4 pad)
#define BS_STR 12            // uints per B row (8 data + 4 pad)
#define GEMM_SMEM ((2 * 128 * AS_STR + 2 * 128 * BS_STR) * 4)   // 81920 B

__global__ void __launch_bounds__(128) gemm_bf16x3_kernel(const float* __restrict__ X,
                                                          int matL, int matR,
                                                          unsigned* __restrict__ Pout,
                                                          float* __restrict__ Qout) {
    unsigned* As0 = sm_dyn;                       // [128][AS_STR]
    unsigned* As1 = sm_dyn + 128 * AS_STR;
    unsigned* Bs0 = sm_dyn + 2 * 128 * AS_STR;    // [128][BS_STR]
    unsigned* Bs1 = Bs0 + 128 * BS_STR;

    int tid = threadIdx.x;
    int warp = tid >> 5, lane = tid & 31;
    int g = lane >> 2, t = lane & 3;
    int wm = (warp >> 1) * 64, wn = (warp & 1) * 64;
    int row0 = blockIdx.x * 128;

    // ---- load & split the full 128x128 A tile into row-major bf16x2 planes ----
    #pragma unroll
    for (int i = 0; i < 32; i++) {
        int slot = tid + 128 * i;              // 0..4095 float4 slots
        int m = slot >> 5;
        int k4 = (slot & 31) * 4;
        int r = row0 + m;
        float4 av = (r < NN) ? *(const float4*)(X + (size_t)r * DD + k4)
                             : make_float4(0.f, 0.f, 0.f, 0.f);
        unsigned p0, p1, q0, q1;
        split2(av.x, av.y, p0, p1);
        split2(av.z, av.w, q0, q1);
        int k2 = k4 >> 1;
        *(uint2*)&As0[m * AS_STR + k2] = make_uint2(p0, q0);
        *(uint2*)&As1[m * AS_STR + k2] = make_uint2(p1, q1);
    }

    // LDSM lane-address components
    // A: lanes 0-7: (m-lo, k-lo); 8-15: (m-hi, k-lo); 16-23: (m-lo, k-hi); 24-31: (m-hi, k-hi)
    int arow = (lane & 7) + ((lane & 8) ? 8 : 0);
    int akb = (lane & 16) ? 16 : 0;               // byte offset within chunk
    // B: lanes 0-7: (n-lo, k-lo); 8-15: (n-lo, k-hi); 16-23: (n-hi, k-lo); 24-31: (n-hi, k-hi)
    int brow = (lane & 7) + ((lane & 16) ? 8 : 0);
    int bkb = (lane & 8) ? 16 : 0;

    unsigned a0base = (unsigned)__cvta_generic_to_shared(As0) + (wm + arow) * (AS_STR * 4) + akb;
    unsigned a1base = (unsigned)__cvta_generic_to_shared(As1) + (wm + arow) * (AS_STR * 4) + akb;
    unsigned b0base = (unsigned)__cvta_generic_to_shared(Bs0) + (wn + brow) * (BS_STR * 4) + bkb;
    unsigned b1base = (unsigned)__cvta_generic_to_shared(Bs1) + (wn + brow) * (BS_STR * 4) + bkb;

    #pragma unroll
    for (int phase = 0; phase < 2; phase++) {
        const unsigned* WT = &g_wspT[phase ? matR : matL][0][0][0];   // [2][128][64]
        float acc[4][8][4];
        #pragma unroll
        for (int a = 0; a < 4; a++)
            #pragma unroll
            for (int b = 0; b < 8; b++)
                #pragma unroll
                for (int c = 0; c < 4; c++) acc[a][b][c] = 0.0f;

        for (int ko2 = 0; ko2 < 64; ko2 += 8) {
            __syncthreads();   // prior Bs consumed (also orders A writes before first reads)
            // load B chunk, both planes: 512 uint4 slots
            #pragma unroll
            for (int i = 0; i < 4; i++) {
                int slot = tid + 128 * i;
                int pl = slot >> 8;
                int rem = slot & 255;
                int n = rem >> 1;
                int half = rem & 1;
                uint4 v = *(const uint4*)(WT + ((size_t)pl * 128 + n) * 64 + ko2 + half * 4);
                *(uint4*)((pl ? Bs1 : Bs0) + n * BS_STR + half * 4) = v;
            }
            __syncthreads();

            // A fragments via LDSM (4 m-tiles x 2 planes)
            unsigned a0f[4][4], a1f[4][4];
            #pragma unroll
            for (int mt = 0; mt < 4; mt++) {
                unsigned off = mt * 16 * (AS_STR * 4) + ko2 * 4;
                ldsm_x4(a0f[mt][0], a0f[mt][1], a0f[mt][2], a0f[mt][3], a0base + off);
                ldsm_x4(a1f[mt][0], a1f[mt][1], a1f[mt][2], a1f[mt][3], a1base + off);
            }
            // B fragments + mma (4 n-tile-pairs x 2 planes)
            #pragma unroll
            for (int ntp = 0; ntp < 4; ntp++) {
                unsigned off = ntp * 16 * (BS_STR * 4);
                unsigned p0r0, p0r1, p0r2, p0r3, p1r0, p1r1, p1r2, p1r3;
                ldsm_x4(p0r0, p0r1, p0r2, p0r3, b0base + off);
                ldsm_x4(p1r0, p1r1, p1r2, p1r3, b1base + off);
                unsigned bh0[2] = {p0r0, p0r1}, bh1[2] = {p0r2, p0r3};
                unsigned bl0[2] = {p1r0, p1r1}, bl1[2] = {p1r2, p1r3};
                #pragma unroll
                for (int mt = 0; mt < 4; mt++) {
                    mma_bf16(acc[mt][2 * ntp], a0f[mt], bh0);
                    mma_bf16(acc[mt][2 * ntp], a0f[mt], bl0);
                    mma_bf16(acc[mt][2 * ntp], a1f[mt], bh0);
                    mma_bf16(acc[mt][2 * ntp + 1], a0f[mt], bh1);
                    mma_bf16(acc[mt][2 * ntp + 1], a0f[mt], bl1);
                    mma_bf16(acc[mt][2 * ntp + 1], a1f[mt], bh1);
                }
            }
        }
        // ---- epilogue ----
        if (phase == 0) {
            #pragma unroll
            for (int mt = 0; mt < 4; mt++) {
                #pragma unroll
                for (int nt = 0; nt < 8; nt++) {
                    int r = row0 + wm + mt * 16 + g;
                    int c = wn + nt * 8 + 2 * t;
                    if (r < NN) Pout[(size_t)r * 64 + (c >> 1)] = pack_bf2(acc[mt][nt][0], acc[mt][nt][1]);
                    if (r + 8 < NN) Pout[(size_t)(r + 8) * 64 + (c >> 1)] = pack_bf2(acc[mt][nt][2], acc[mt][nt][3]);
                }
            }
        } else {
            #pragma unroll
            for (int mt = 0; mt < 4; mt++) {
                #pragma unroll
                for (int nt = 0; nt < 8; nt++) {
                    int r = row0 + wm + mt * 16 + g;
                    int c = wn + nt * 8 + 2 * t;
                    if (r < NN)
                        *(float2*)(Qout + (size_t)r * DD + c) = make_float2(acc[mt][nt][0], acc[mt][nt][1]);
                    if (r + 8 < NN)
                        *(float2*)(Qout + (size_t)(r + 8) * DD + c) = make_float2(acc[mt][nt][2], acc[mt][nt][3]);
                }
            }
        }
    }
}

// ---------------- degree / counts / scan / place ----------------
__global__ void deg_kernel(const void* __restrict__ ei) {
    int e = blockIdx.x * blockDim.x + threadIdx.x;
    if (e >= EE) return;
    unsigned d = (unsigned)ld_ei(ei, (long long)EE + e);
    if (d >= NN) return;
    atomicAdd(&g_degi[d], 1);
}

__global__ void __launch_bounds__(256) cnt_hist_kernel(const void* __restrict__ batch) {
    __shared__ int sh[NG];
    if (threadIdx.x < NG) sh[threadIdx.x] = 0;
    __syncthreads();
    int i = blockIdx.x * blockDim.x + threadIdx.x;
    if (i < NN) {
        unsigned g = (unsigned)ld_b(batch, i);
        if (g < NG) atomicAdd(&sh[g], 1);
    }
    __syncthreads();
    if (threadIdx.x < NG && sh[threadIdx.x] != 0) atomicAdd(&g_cnti[threadIdx.x], sh[threadIdx.x]);
}

__global__ void __launch_bounds__(256) scan1_kernel() {
    __shared__ int sdata[256];
    int t = threadIdx.x;
    int i = blockIdx.x * 256 + t;
    int v = (i < NN) ? g_degi[i] : 0;
    sdata[t] = v;
    __syncthreads();
    #pragma unroll
    for (int off = 1; off < 256; off <<= 1) {
        int x = (t >= off) ? sdata[t - off] : 0;
        __syncthreads();
        sdata[t] += x;
        __syncthreads();
    }
    int incl = sdata[t];
    if (i < NN) g_start[i] = incl - v;
    if (t == 255) g_bsum[blockIdx.x] = incl;
}

__global__ void __launch_bounds__(512) scan2_kernel(int nb) {
    __shared__ int sdata[512];
    int t = threadIdx.x;
    int v = (t < nb) ? g_bsum[t] : 0;
    sdata[t] = v;
    __syncthreads();
    #pragma unroll
    for (int off = 1; off < 512; off <<= 1) {
        int x = (t >= off) ? sdata[t - off] : 0;
        __syncthreads();
        sdata[t] += x;
        __syncthreads();
    }
    if (t < nb) g_bsum[t] = sdata[t] - v;
    if (t < NG) g_cinv[t] = 1.0f / fmaxf((float)g_cnti[t], 1.0f);
}

__global__ void __launch_bounds__(256) scan3_kernel() {
    int i = blockIdx.x * 256 + threadIdx.x;
    if (i >= NN) return;
    int s = g_start[i] + g_bsum[i >> 8];
    g_start[i] = s;
    g_cursor[i] = s;
    g_winv[i] = 1.0f / fmaxf((float)g_degi[i], 1.0f);
}

__global__ void __launch_bounds__(256) place_kernel(const void* __restrict__ ei) {
    int e = blockIdx.x * blockDim.x + threadIdx.x;
    if (e >= EE) return;
    unsigned s = (unsigned)ld_ei(ei, e);
    unsigned d = (unsigned)ld_ei(ei, (long long)EE + e);
    if (s >= NN || d >= NN) return;
    int pos = atomicAdd(&g_cursor[d], 1);
    g_csr[pos] = (int)s;
}

// ---------------- CSR gather (bf16 P) ----------------
__device__ __forceinline__ void acc_bf2(float4& acc, uint2 v) {
    acc.x += __uint_as_float(v.x << 16);
    acc.y += __uint_as_float(v.x & 0xFFFF0000u);
    acc.z += __uint_as_float(v.y << 16);
    acc.w += __uint_as_float(v.y & 0xFFFF0000u);
}

__global__ void __launch_bounds__(256) gather_kernel(const unsigned* __restrict__ P,
                                                     const float* __restrict__ Q,
                                                     const float* __restrict__ bias,
                                                     float* __restrict__ H) {
    int node = blockIdx.x * 8 + (threadIdx.x >> 5);
    int lane = threadIdx.x & 31;
    int s = g_start[node];
    int d = g_degi[node];
    float4 acc = make_float4(0.f, 0.f, 0.f, 0.f);
    for (int j = 0; j < d; j++) {
        int src = g_csr[s + j];
        uint2 v = ((const uint2*)(P + (size_t)src * 64))[lane];
        acc_bf2(acc, v);
    }
    float w = g_winv[node];
    float4 q = ((const float4*)(Q + (size_t)node * DD))[lane];
    float4 b = ((const float4*)bias)[lane];
    float4 o;
    o.x = fmaxf(acc.x * w + q.x + b.x, 0.0f);
    o.y = fmaxf(acc.y * w + q.y + b.y, 0.0f);
    o.z = fmaxf(acc.z * w + q.z + b.z, 0.0f);
    o.w = fmaxf(acc.w * w + q.w + b.w, 0.0f);
    ((float4*)(H + (size_t)node * DD))[lane] = o;
}

// ---------------- layer-2 gather fused with layer-3 projection -> z ----------------
__global__ void __launch_bounds__(256) gather2z_kernel(const unsigned* __restrict__ P,
                                                       const float* __restrict__ Q,
                                                       const float* __restrict__ bias) {
    int node = blockIdx.x * 8 + (threadIdx.x >> 5);
    int lane = threadIdx.x & 31;
    int s = g_start[node];
    int d = g_degi[node];
    float4 acc = make_float4(0.f, 0.f, 0.f, 0.f);
    for (int j = 0; j < d; j++) {
        int src = g_csr[s + j];
        uint2 v = ((const uint2*)(P + (size_t)src * 64))[lane];
        acc_bf2(acc, v);
    }
    float w = g_winv[node];
    float4 q = ((const float4*)(Q + (size_t)node * DD))[lane];
    float4 b = ((const float4*)bias)[lane];
    float hv[4];
    hv[0] = fmaxf(acc.x * w + q.x + b.x, 0.0f);
    hv[1] = fmaxf(acc.y * w + q.y + b.y, 0.0f);
    hv[2] = fmaxf(acc.z * w + q.z + b.z, 0.0f);
    hv[3] = fmaxf(acc.w * w + q.w + b.w, 0.0f);
    float s0 = 0.f, s1 = 0.f, s2 = 0.f, s3 = 0.f;
    #pragma unroll
    for (int j = 0; j < 4; j++) {
        int k = lane * 4 + j;
        s0 += hv[j] * g_Wcl[k * 2 + 0];
        s1 += hv[j] * g_Wcl[k * 2 + 1];
        s2 += hv[j] * g_Wcr[k * 2 + 0];
        s3 += hv[j] * g_Wcr[k * 2 + 1];
    }
    #pragma unroll
    for (int o = 16; o > 0; o >>= 1) {
        s0 += __shfl_down_sync(0xFFFFFFFFu, s0, o);
        s1 += __shfl_down_sync(0xFFFFFFFFu, s1, o);
        s2 += __shfl_down_sync(0xFFFFFFFFu, s2, o);
        s3 += __shfl_down_sync(0xFFFFFFFFu, s3, o);
    }
    if (lane == 0) ((float4*)g_z)[node] = make_float4(s0, s1, s2, s3);
}

// ---------------- layer-3 fold ----------------
__global__ void foldW_kernel(const float* __restrict__ Wl3, const float* __restrict__ Wr3,
                             const float* __restrict__ bl3, const float* __restrict__ Wlin,
                             const float* __restrict__ blin) {
    int k = threadIdx.x;
    float a0 = 0.f, a1 = 0.f, b0 = 0.f, b1 = 0.f;
    for (int m = 0; m < DD; m++) {
        float wl = Wl3[k * DD + m], wr = Wr3[k * DD + m];
        float l0 = Wlin[m * 2 + 0], l1 = Wlin[m * 2 + 1];
        a0 += wl * l0; a1 += wl * l1;
        b0 += wr * l0; b1 += wr * l1;
    }
    g_Wcl[k * 2 + 0] = a0; g_Wcl[k * 2 + 1] = a1;
    g_Wcr[k * 2 + 0] = b0; g_Wcr[k * 2 + 1] = b1;
    if (k < 2) {
        float cv = blin[k];
        for (int m = 0; m < DD; m++) cv += bl3[m] * Wlin[m * 2 + k];
        g_cb[k] = cv;
    }
}

// ---------------- layer-3 pooled reduction ----------------
__global__ void __launch_bounds__(256) pool3_kernel(const void* __restrict__ batch) {
    __shared__ float sh[NG * 2];
    for (int i = threadIdx.x; i < NG * 2; i += blockDim.x) sh[i] = 0.0f;
    __syncthreads();
    int n = blockIdx.x * 256 + threadIdx.x;
    if (n < NN) {
        int s = g_start[n], d = g_degi[n];
        float s0 = 0.f, s1 = 0.f;
        for (int j = 0; j < d; j++) {
            int src = g_csr[s + j];
            float2 zl = *(const float2*)(g_z + (size_t)src * 4);
            s0 += zl.x; s1 += zl.y;
        }
        float w = g_winv[n];
        unsigned gg = (unsigned)ld_b(batch, n);
        if (gg < NG) {
            float ci = g_cinv[gg];
            float2 zr = *(const float2*)(g_z + (size_t)n * 4 + 2);
            atomicAdd(&sh[gg * 2 + 0], ci * (w * s0 + zr.x));
            atomicAdd(&sh[gg * 2 + 1], ci * (w * s1 + zr.y));
        }
    }
    __syncthreads();
    for (int i = threadIdx.x; i < NG * 2; i += blockDim.x)
        if (sh[i] != 0.0f) atomicAdd(&g_acc[i], sh[i]);
}

__global__ void finalize_kernel(float* __restrict__ out) {
    int t = threadIdx.x;
    if (t < NG * 2) out[t] = g_acc[t] + g_cb[t & 1];
}

// ---------------- host launcher ----------------
extern "C" void kernel_launch(void* const* d_in, const int* in_sizes, int n_in,
                              void* d_out, int out_size) {
    const float* x = (const float*)d_in[0];
    const void* ei = d_in[1];
    const void* batch = d_in[2];
    const float* Wl1 = (const float*)d_in[3];
    const float* bl1 = (const float*)d_in[4];
    const float* Wr1 = (const float*)d_in[5];
    const float* Wl2 = (const float*)d_in[6];
    const float* bl2 = (const float*)d_in[7];
    const float* Wr2 = (const float*)d_in[8];
    const float* Wl3 = (const float*)d_in[9];
    const float* bl3 = (const float*)d_in[10];
    const float* Wr3 = (const float*)d_in[11];
    const float* Wlin = (const float*)d_in[12];
    const float* blin = (const float*)d_in[13];
    float* out = (float*)d_out;

    // __device__ symbols are not host pointers: resolve real addresses.
    unsigned* pp = nullptr;
    float *qp = nullptr, *h1p = nullptr;
    cudaGetSymbolAddress((void**)&pp, g_pb);
    cudaGetSymbolAddress((void**)&qp, g_q);
    cudaGetSymbolAddress((void**)&h1p, g_h1);

    cudaFuncSetAttribute(gemm_bf16x3_kernel,
                         cudaFuncAttributeMaxDynamicSharedMemorySize, GEMM_SMEM);

    const int nb = (NN + 255) / 256;           // 391
    const int gemm_blocks = (NN + 127) / 128;  // 782

    detect_kernel<<<1, 1>>>(ei, batch);
    zero_small_kernel<<<nb, 256>>>();
    presplit_kernel<<<128, 256>>>(Wl1, Wr1, Wl2, Wr2);
    gemm_bf16x3_kernel<<<gemm_blocks, 128, GEMM_SMEM>>>(x, 0, 1, pp, qp);   // profile slot
    deg_kernel<<<(EE + 255) / 256, 256>>>(ei);
    cnt_hist_kernel<<<nb, 256>>>(batch);
    scan1_kernel<<<nb, 256>>>();
    scan2_kernel<<<1, 512>>>(nb);
    scan3_kernel<<<nb, 256>>>();
    place_kernel<<<(EE + 255) / 256, 256>>>(ei);

    gather_kernel<<<NN / 8, 256>>>(pp, qp, bl1, h1p);
    gemm_bf16x3_kernel<<<gemm_blocks, 128, GEMM_SMEM>>>(h1p, 2, 3, pp, qp);
    foldW_kernel<<<1, 128>>>(Wl3, Wr3, bl3, Wlin, blin);
    gather2z_kernel<<<NN / 8, 256>>>(pp, qp, bl2);
    pool3_kernel<<<nb, 256>>>(batch);
    finalize_kernel<<<1, 128>>>(out);
}

// round 9
// speedup vs baseline: 1.1340x; 1.0423x over previous
#include <cuda_runtime.h>
#include <cstdint>

#define NN 100000
#define EE 1600000
#define DD 128
#define NG 64

// ---------------- scratch (static device globals; no allocation) ----------------
__device__ int      g_ei64, g_b64;
__device__ int      g_degi[NN];
__device__ int      g_start[NN];
__device__ int      g_cursor[NN];
__device__ int      g_bsum[512];
__device__ int      g_cnti[NG];
__device__ int      g_csr[EE];
__device__ float    g_winv[NN];
__device__ float    g_cinv[NG];
__device__ unsigned g_pb[(size_t)NN * 64];   // P packed bf16x2 (row = 64 uints)
__device__ unsigned g_qb[(size_t)NN * 64];   // Q packed bf16x2
__device__ float    g_h1[(size_t)NN * DD];
__device__ float    g_z[(size_t)NN * 4];
__device__ unsigned g_wspT[4][2][DD][64];    // pre-split W, transposed [mat][plane][n][k2] bf16x2
__device__ float    g_Wcl[DD * 2];
__device__ float    g_Wcr[DD * 2];
__device__ float    g_cb[2];
__device__ float    g_acc[NG * 2];

// ---------------- helpers ----------------
__device__ __forceinline__ unsigned pack_bf2(float lo, float hi) {
    unsigned r;
    asm("cvt.rn.bf16x2.f32 %0, %1, %2;" : "=r"(r) : "f"(hi), "f"(lo));
    return r;
}
__device__ __forceinline__ void split2(float x0, float x1, unsigned& p0, unsigned& p1) {
    p0 = pack_bf2(x0, x1);
    float h0 = __uint_as_float(p0 << 16);
    float h1 = __uint_as_float(p0 & 0xFFFF0000u);
    p1 = pack_bf2(x0 - h0, x1 - h1);
}
__device__ __forceinline__ void mma_bf16(float* d, const unsigned* a, const unsigned* b) {
    asm volatile(
        "mma.sync.aligned.m16n8k16.row.col.f32.bf16.bf16.f32 "
        "{%0,%1,%2,%3}, {%4,%5,%6,%7}, {%8,%9}, {%0,%1,%2,%3};"
        : "+f"(d[0]), "+f"(d[1]), "+f"(d[2]), "+f"(d[3])
        : "r"(a[0]), "r"(a[1]), "r"(a[2]), "r"(a[3]), "r"(b[0]), "r"(b[1]));
}
__device__ __forceinline__ void ldsm_x4(unsigned& r0, unsigned& r1, unsigned& r2, unsigned& r3,
                                        unsigned saddr) {
    asm volatile("ldmatrix.sync.aligned.m8n8.x4.shared.b16 {%0,%1,%2,%3}, [%4];"
                 : "=r"(r0), "=r"(r1), "=r"(r2), "=r"(r3) : "r"(saddr));
}

// ---------------- dtype detection (int32 vs int64) ----------------
__global__ void detect_kernel(const void* ei, const void* batch) {
    const long long* p = (const long long*)ei;
    bool e64 = true;
    #pragma unroll
    for (int i = 0; i < 16; i++) {
        long long v = p[(size_t)i * 99991];
        if (v < 0 || v >= NN) e64 = false;
    }
    g_ei64 = e64 ? 1 : 0;
    const long long* q = (const long long*)batch;
    bool b64 = true;
    #pragma unroll
    for (int i = 0; i < 8; i++) {
        long long v = q[NN / 2 - 1 - i * 37];
        if (v < 0 || v >= NG) b64 = false;
    }
    g_b64 = b64 ? 1 : 0;
}
__device__ __forceinline__ int ld_ei(const void* p, long long i) {
    return g_ei64 ? (int)((const long long*)p)[i] : ((const int*)p)[i];
}
__device__ __forceinline__ int ld_b(const void* p, long long i) {
    return g_b64 ? (int)((const long long*)p)[i] : ((const int*)p)[i];
}

// ---------------- small init ----------------
__global__ void zero_small_kernel() {
    int i = blockIdx.x * blockDim.x + threadIdx.x;
    if (i < NN) g_degi[i] = 0;
    if (i < NG) g_cnti[i] = 0;
    if (i < NG * 2) g_acc[i] = 0.0f;
}

// ---------------- pre-split W into bf16 hi/lo planes, transposed [n][k2] ----------------
__global__ void __launch_bounds__(256) presplit_kernel(const float* __restrict__ Wl1,
                                                       const float* __restrict__ Wr1,
                                                       const float* __restrict__ Wl2,
                                                       const float* __restrict__ Wr2) {
    int idx = blockIdx.x * 256 + threadIdx.x;   // 0..32767
    int mat = idx >> 13;
    int rem = idx & 8191;
    int k2 = rem >> 7;
    int n = rem & 127;
    const float* W = (mat == 0) ? Wl1 : (mat == 1) ? Wr1 : (mat == 2) ? Wl2 : Wr2;
    float w0 = W[(2 * k2) * DD + n];
    float w1 = W[(2 * k2 + 1) * DD + n];
    unsigned p0, p1;
    split2(w0, w1, p0, p1);
    g_wspT[mat][0][n][k2] = p0;
    g_wspT[mat][1][n][k2] = p1;
}

// ---------------- bf16x3 GEMM via ldmatrix, double-buffered B ----------------
// 128 threads, 4 warps (2x2 grid of 64x64 warp tiles), block tile 128x128.
// A split resident in smem (272B row stride); B chunks double-buffered (48B n-stride).
extern __shared__ unsigned sm_dyn[];
#define AS_STR 68            // uints per A row (64 data + 4 pad)
#define BS_STR 12            // uints per B row (8 data + 4 pad)
#define GEMM_SMEM ((2 * 128 * AS_STR + 4 * 128 * BS_STR) * 4)   // 94208 B

__global__ void __launch_bounds__(128) gemm_bf16x3_kernel(const float* __restrict__ X,
                                                          int matL, int matR,
                                                          unsigned* __restrict__ Pout,
                                                          unsigned* __restrict__ Qout) {
    unsigned* As0 = sm_dyn;                       // [128][AS_STR]
    unsigned* As1 = sm_dyn + 128 * AS_STR;
    unsigned* Bbuf[2][2];
    Bbuf[0][0] = sm_dyn + 2 * 128 * AS_STR;       // [buf][plane][128][BS_STR]
    Bbuf[0][1] = Bbuf[0][0] + 128 * BS_STR;
    Bbuf[1][0] = Bbuf[0][1] + 128 * BS_STR;
    Bbuf[1][1] = Bbuf[1][0] + 128 * BS_STR;

    int tid = threadIdx.x;
    int warp = tid >> 5, lane = tid & 31;
    int g = lane >> 2, t = lane & 3;
    int wm = (warp >> 1) * 64, wn = (warp & 1) * 64;
    int row0 = blockIdx.x * 128;

    // ---- load & split the full 128x128 A tile ----
    #pragma unroll
    for (int i = 0; i < 32; i++) {
        int slot = tid + 128 * i;              // 0..4095 float4 slots
        int m = slot >> 5;
        int k4 = (slot & 31) * 4;
        int r = row0 + m;
        float4 av = (r < NN) ? *(const float4*)(X + (size_t)r * DD + k4)
                             : make_float4(0.f, 0.f, 0.f, 0.f);
        unsigned p0, p1, q0, q1;
        split2(av.x, av.y, p0, p1);
        split2(av.z, av.w, q0, q1);
        int k2 = k4 >> 1;
        *(uint2*)&As0[m * AS_STR + k2] = make_uint2(p0, q0);
        *(uint2*)&As1[m * AS_STR + k2] = make_uint2(p1, q1);
    }

    // LDSM lane-address components (same mapping as validated R7)
    int arow = (lane & 7) + ((lane & 8) ? 8 : 0);
    int akb = (lane & 16) ? 16 : 0;
    int brow = (lane & 7) + ((lane & 16) ? 8 : 0);
    int bkb = (lane & 8) ? 16 : 0;

    unsigned a0base = (unsigned)__cvta_generic_to_shared(As0) + (wm + arow) * (AS_STR * 4) + akb;
    unsigned a1base = (unsigned)__cvta_generic_to_shared(As1) + (wm + arow) * (AS_STR * 4) + akb;
    unsigned bbase[2][2];
    #pragma unroll
    for (int bf = 0; bf < 2; bf++)
        #pragma unroll
        for (int pl = 0; pl < 2; pl++)
            bbase[bf][pl] = (unsigned)__cvta_generic_to_shared(Bbuf[bf][pl]) +
                            (wn + brow) * (BS_STR * 4) + bkb;

    const unsigned* WTs[2] = {&g_wspT[matL][0][0][0], &g_wspT[matR][0][0][0]};

    float acc[4][8][4];
    #pragma unroll
    for (int a = 0; a < 4; a++)
        #pragma unroll
        for (int b = 0; b < 8; b++)
            #pragma unroll
            for (int c = 0; c < 4; c++) acc[a][b][c] = 0.0f;

    // ---- preload B chunk 0 (phase 0) into buffer 0 ----
    #pragma unroll
    for (int i = 0; i < 4; i++) {
        int slot = tid + 128 * i;       // 512 uint4 slots
        int pl = slot >> 8;
        int rem = slot & 255;
        int n = rem >> 1;
        int half = rem & 1;
        uint4 v = *(const uint4*)(WTs[0] + ((size_t)pl * 128 + n) * 64 + half * 4);
        *(uint4*)(Bbuf[0][pl] + n * BS_STR + half * 4) = v;
    }
    __syncthreads();   // A split + chunk0 visible

    // ---- 16-chunk pipeline: chunks 0..7 = phase 0 (matL), 8..15 = phase 1 (matR) ----
    #pragma unroll
    for (int c = 0; c < 16; c++) {
        const int cur = c & 1;
        // prefetch next chunk into registers
        uint4 pf[4];
        if (c < 15) {
            const unsigned* WT = WTs[(c + 1) >> 3];
            int ko2n = ((c + 1) & 7) * 8;
            #pragma unroll
            for (int i = 0; i < 4; i++) {
                int slot = tid + 128 * i;
                int pl = slot >> 8;
                int rem = slot & 255;
                int n = rem >> 1;
                int half = rem & 1;
                pf[i] = *(const uint4*)(WT + ((size_t)pl * 128 + n) * 64 + ko2n + half * 4);
            }
        }
        // compute chunk c from buffer cur
        int ko2 = (c & 7) * 8;
        unsigned a0f[4][4], a1f[4][4];
        #pragma unroll
        for (int mt = 0; mt < 4; mt++) {
            unsigned off = mt * 16 * (AS_STR * 4) + ko2 * 4;
            ldsm_x4(a0f[mt][0], a0f[mt][1], a0f[mt][2], a0f[mt][3], a0base + off);
            ldsm_x4(a1f[mt][0], a1f[mt][1], a1f[mt][2], a1f[mt][3], a1base + off);
        }
        #pragma unroll
        for (int ntp = 0; ntp < 4; ntp++) {
            unsigned off = ntp * 16 * (BS_STR * 4);
            unsigned p0r0, p0r1, p0r2, p0r3, p1r0, p1r1, p1r2, p1r3;
            ldsm_x4(p0r0, p0r1, p0r2, p0r3, bbase[cur][0] + off);
            ldsm_x4(p1r0, p1r1, p1r2, p1r3, bbase[cur][1] + off);
            unsigned bh0[2] = {p0r0, p0r1}, bh1[2] = {p0r2, p0r3};
            unsigned bl0[2] = {p1r0, p1r1}, bl1[2] = {p1r2, p1r3};
            #pragma unroll
            for (int mt = 0; mt < 4; mt++) {
                mma_bf16(acc[mt][2 * ntp], a0f[mt], bh0);
                mma_bf16(acc[mt][2 * ntp], a0f[mt], bl0);
                mma_bf16(acc[mt][2 * ntp], a1f[mt], bh0);
                mma_bf16(acc[mt][2 * ntp + 1], a0f[mt], bh1);
                mma_bf16(acc[mt][2 * ntp + 1], a0f[mt], bl1);
                mma_bf16(acc[mt][2 * ntp + 1], a1f[mt], bh1);
            }
        }
        // end of phase 0: write P (bf16x2), reset accumulators
        if (c == 7) {
            #pragma unroll
            for (int mt = 0; mt < 4; mt++) {
                #pragma unroll
                for (int nt = 0; nt < 8; nt++) {
                    int r = row0 + wm + mt * 16 + g;
                    int cc = wn + nt * 8 + 2 * t;
                    if (r < NN)
                        Pout[(size_t)r * 64 + (cc >> 1)] = pack_bf2(acc[mt][nt][0], acc[mt][nt][1]);
                    if (r + 8 < NN)
                        Pout[(size_t)(r + 8) * 64 + (cc >> 1)] = pack_bf2(acc[mt][nt][2], acc[mt][nt][3]);
                    acc[mt][nt][0] = acc[mt][nt][1] = acc[mt][nt][2] = acc[mt][nt][3] = 0.0f;
                }
            }
        }
        // store prefetched chunk into the other buffer
        if (c < 15) {
            #pragma unroll
            for (int i = 0; i < 4; i++) {
                int slot = tid + 128 * i;
                int pl = slot >> 8;
                int rem = slot & 255;
                int n = rem >> 1;
                int half = rem & 1;
                *(uint4*)(Bbuf[cur ^ 1][pl] + n * BS_STR + half * 4) = pf[i];
            }
        }
        __syncthreads();
    }

    // ---- phase-1 epilogue: write Q (bf16x2) ----
    #pragma unroll
    for (int mt = 0; mt < 4; mt++) {
        #pragma unroll
        for (int nt = 0; nt < 8; nt++) {
            int r = row0 + wm + mt * 16 + g;
            int cc = wn + nt * 8 + 2 * t;
            if (r < NN)
                Qout[(size_t)r * 64 + (cc >> 1)] = pack_bf2(acc[mt][nt][0], acc[mt][nt][1]);
            if (r + 8 < NN)
                Qout[(size_t)(r + 8) * 64 + (cc >> 1)] = pack_bf2(acc[mt][nt][2], acc[mt][nt][3]);
        }
    }
}

// ---------------- fused degree + batch histogram ----------------
__global__ void __launch_bounds__(256) deg_cnt_kernel(const void* __restrict__ ei,
                                                      const void* __restrict__ batch) {
    __shared__ int sh[NG];
    if (threadIdx.x < NG) sh[threadIdx.x] = 0;
    __syncthreads();
    int e = blockIdx.x * 256 + threadIdx.x;
    if (e < EE) {
        unsigned d = (unsigned)ld_ei(ei, (long long)EE + e);
        if (d < NN) atomicAdd(&g_degi[d], 1);
    }
    if (e < NN) {
        unsigned g = (unsigned)ld_b(batch, e);
        if (g < NG) atomicAdd(&sh[g], 1);
    }
    __syncthreads();
    if (threadIdx.x < NG && sh[threadIdx.x] != 0) atomicAdd(&g_cnti[threadIdx.x], sh[threadIdx.x]);
}

// ---------------- scans / CSR placement ----------------
__global__ void __launch_bounds__(256) scan1_kernel() {
    __shared__ int sdata[256];
    int t = threadIdx.x;
    int i = blockIdx.x * 256 + t;
    int v = (i < NN) ? g_degi[i] : 0;
    sdata[t] = v;
    __syncthreads();
    #pragma unroll
    for (int off = 1; off < 256; off <<= 1) {
        int x = (t >= off) ? sdata[t - off] : 0;
        __syncthreads();
        sdata[t] += x;
        __syncthreads();
    }
    int incl = sdata[t];
    if (i < NN) g_start[i] = incl - v;
    if (t == 255) g_bsum[blockIdx.x] = incl;
}

__global__ void __launch_bounds__(512) scan2_kernel(int nb) {
    __shared__ int sdata[512];
    int t = threadIdx.x;
    int v = (t < nb) ? g_bsum[t] : 0;
    sdata[t] = v;
    __syncthreads();
    #pragma unroll
    for (int off = 1; off < 512; off <<= 1) {
        int x = (t >= off) ? sdata[t - off] : 0;
        __syncthreads();
        sdata[t] += x;
        __syncthreads();
    }
    if (t < nb) g_bsum[t] = sdata[t] - v;
    if (t < NG) g_cinv[t] = 1.0f / fmaxf((float)g_cnti[t], 1.0f);
}

__global__ void __launch_bounds__(256) scan3_kernel() {
    int i = blockIdx.x * 256 + threadIdx.x;
    if (i >= NN) return;
    int s = g_start[i] + g_bsum[i >> 8];
    g_start[i] = s;
    g_cursor[i] = s;
    g_winv[i] = 1.0f / fmaxf((float)g_degi[i], 1.0f);
}

__global__ void __launch_bounds__(256) place_kernel(const void* __restrict__ ei) {
    int e = blockIdx.x * blockDim.x + threadIdx.x;
    if (e >= EE) return;
    unsigned s = (unsigned)ld_ei(ei, e);
    unsigned d = (unsigned)ld_ei(ei, (long long)EE + e);
    if (s >= NN || d >= NN) return;
    int pos = atomicAdd(&g_cursor[d], 1);
    g_csr[pos] = (int)s;
}

// ---------------- CSR gather (bf16 P + bf16 Q) ----------------
__device__ __forceinline__ void acc_bf2(float4& acc, uint2 v) {
    acc.x += __uint_as_float(v.x << 16);
    acc.y += __uint_as_float(v.x & 0xFFFF0000u);
    acc.z += __uint_as_float(v.y << 16);
    acc.w += __uint_as_float(v.y & 0xFFFF0000u);
}

__global__ void __launch_bounds__(256) gather_kernel(const unsigned* __restrict__ P,
                                                     const unsigned* __restrict__ Q,
                                                     const float* __restrict__ bias,
                                                     float* __restrict__ H) {
    int node = blockIdx.x * 8 + (threadIdx.x >> 5);
    int lane = threadIdx.x & 31;
    int s = g_start[node];
    int d = g_degi[node];
    float4 acc = make_float4(0.f, 0.f, 0.f, 0.f);
    for (int j = 0; j < d; j++) {
        int src = g_csr[s + j];
        uint2 v = ((const uint2*)(P + (size_t)src * 64))[lane];
        acc_bf2(acc, v);
    }
    float w = g_winv[node];
    float4 q = make_float4(0.f, 0.f, 0.f, 0.f);
    acc_bf2(q, ((const uint2*)(Q + (size_t)node * 64))[lane]);
    float4 b = ((const float4*)bias)[lane];
    float4 o;
    o.x = fmaxf(acc.x * w + q.x + b.x, 0.0f);
    o.y = fmaxf(acc.y * w + q.y + b.y, 0.0f);
    o.z = fmaxf(acc.z * w + q.z + b.z, 0.0f);
    o.w = fmaxf(acc.w * w + q.w + b.w, 0.0f);
    ((float4*)(H + (size_t)node * DD))[lane] = o;
}

// ---------------- layer-2 gather fused with layer-3 projection -> z ----------------
__global__ void __launch_bounds__(256) gather2z_kernel(const unsigned* __restrict__ P,
                                                       const unsigned* __restrict__ Q,
                                                       const float* __restrict__ bias) {
    int node = blockIdx.x * 8 + (threadIdx.x >> 5);
    int lane = threadIdx.x & 31;
    int s = g_start[node];
    int d = g_degi[node];
    float4 acc = make_float4(0.f, 0.f, 0.f, 0.f);
    for (int j = 0; j < d; j++) {
        int src = g_csr[s + j];
        uint2 v = ((const uint2*)(P + (size_t)src * 64))[lane];
        acc_bf2(acc, v);
    }
    float w = g_winv[node];
    float4 q = make_float4(0.f, 0.f, 0.f, 0.f);
    acc_bf2(q, ((const uint2*)(Q + (size_t)node * 64))[lane]);
    float4 b = ((const float4*)bias)[lane];
    float hv[4];
    hv[0] = fmaxf(acc.x * w + q.x + b.x, 0.0f);
    hv[1] = fmaxf(acc.y * w + q.y + b.y, 0.0f);
    hv[2] = fmaxf(acc.z * w + q.z + b.z, 0.0f);
    hv[3] = fmaxf(acc.w * w + q.w + b.w, 0.0f);
    float s0 = 0.f, s1 = 0.f, s2 = 0.f, s3 = 0.f;
    #pragma unroll
    for (int j = 0; j < 4; j++) {
        int k = lane * 4 + j;
        s0 += hv[j] * g_Wcl[k * 2 + 0];
        s1 += hv[j] * g_Wcl[k * 2 + 1];
        s2 += hv[j] * g_Wcr[k * 2 + 0];
        s3 += hv[j] * g_Wcr[k * 2 + 1];
    }
    #pragma unroll
    for (int o = 16; o > 0; o >>= 1) {
        s0 += __shfl_down_sync(0xFFFFFFFFu, s0, o);
        s1 += __shfl_down_sync(0xFFFFFFFFu, s1, o);
        s2 += __shfl_down_sync(0xFFFFFFFFu, s2, o);
        s3 += __shfl_down_sync(0xFFFFFFFFu, s3, o);
    }
    if (lane == 0) ((float4*)g_z)[node] = make_float4(s0, s1, s2, s3);
}

// ---------------- layer-3 fold ----------------
__global__ void foldW_kernel(const float* __restrict__ Wl3, const float* __restrict__ Wr3,
                             const float* __restrict__ bl3, const float* __restrict__ Wlin,
                             const float* __restrict__ blin) {
    int k = threadIdx.x;
    float a0 = 0.f, a1 = 0.f, b0 = 0.f, b1 = 0.f;
    for (int m = 0; m < DD; m++) {
        float wl = Wl3[k * DD + m], wr = Wr3[k * DD + m];
        float l0 = Wlin[m * 2 + 0], l1 = Wlin[m * 2 + 1];
        a0 += wl * l0; a1 += wl * l1;
        b0 += wr * l0; b1 += wr * l1;
    }
    g_Wcl[k * 2 + 0] = a0; g_Wcl[k * 2 + 1] = a1;
    g_Wcr[k * 2 + 0] = b0; g_Wcr[k * 2 + 1] = b1;
    if (k < 2) {
        float cv = blin[k];
        for (int m = 0; m < DD; m++) cv += bl3[m] * Wlin[m * 2 + k];
        g_cb[k] = cv;
    }
}

// ---------------- layer-3 pooled reduction ----------------
__global__ void __launch_bounds__(256) pool3_kernel(const void* __restrict__ batch) {
    __shared__ float sh[NG * 2];
    for (int i = threadIdx.x; i < NG * 2; i += blockDim.x) sh[i] = 0.0f;
    __syncthreads();
    int n = blockIdx.x * 256 + threadIdx.x;
    if (n < NN) {
        int s = g_start[n], d = g_degi[n];
        float s0 = 0.f, s1 = 0.f;
        for (int j = 0; j < d; j++) {
            int src = g_csr[s + j];
            float2 zl = *(const float2*)(g_z + (size_t)src * 4);
            s0 += zl.x; s1 += zl.y;
        }
        float w = g_winv[n];
        unsigned gg = (unsigned)ld_b(batch, n);
        if (gg < NG) {
            float ci = g_cinv[gg];
            float2 zr = *(const float2*)(g_z + (size_t)n * 4 + 2);
            atomicAdd(&sh[gg * 2 + 0], ci * (w * s0 + zr.x));
            atomicAdd(&sh[gg * 2 + 1], ci * (w * s1 + zr.y));
        }
    }
    __syncthreads();
    for (int i = threadIdx.x; i < NG * 2; i += blockDim.x)
        if (sh[i] != 0.0f) atomicAdd(&g_acc[i], sh[i]);
}

__global__ void finalize_kernel(float* __restrict__ out) {
    int t = threadIdx.x;
    if (t < NG * 2) out[t] = g_acc[t] + g_cb[t & 1];
}

// ---------------- host launcher ----------------
extern "C" void kernel_launch(void* const* d_in, const int* in_sizes, int n_in,
                              void* d_out, int out_size) {
    const float* x = (const float*)d_in[0];
    const void* ei = d_in[1];
    const void* batch = d_in[2];
    const float* Wl1 = (const float*)d_in[3];
    const float* bl1 = (const float*)d_in[4];
    const float* Wr1 = (const float*)d_in[5];
    const float* Wl2 = (const float*)d_in[6];
    const float* bl2 = (const float*)d_in[7];
    const float* Wr2 = (const float*)d_in[8];
    const float* Wl3 = (const float*)d_in[9];
    const float* bl3 = (const float*)d_in[10];
    const float* Wr3 = (const float*)d_in[11];
    const float* Wlin = (const float*)d_in[12];
    const float* blin = (const float*)d_in[13];
    float* out = (float*)d_out;

    // __device__ symbols are not host pointers: resolve real addresses.
    unsigned *pp = nullptr, *qp = nullptr;
    float* h1p = nullptr;
    cudaGetSymbolAddress((void**)&pp, g_pb);
    cudaGetSymbolAddress((void**)&qp, g_qb);
    cudaGetSymbolAddress((void**)&h1p, g_h1);

    cudaFuncSetAttribute(gemm_bf16x3_kernel,
                         cudaFuncAttributeMaxDynamicSharedMemorySize, GEMM_SMEM);

    const int nb = (NN + 255) / 256;           // 391
    const int gemm_blocks = (NN + 127) / 128;  // 782

    detect_kernel<<<1, 1>>>(ei, batch);
    zero_small_kernel<<<nb, 256>>>();
    presplit_kernel<<<128, 256>>>(Wl1, Wr1, Wl2, Wr2);
    gemm_bf16x3_kernel<<<gemm_blocks, 128, GEMM_SMEM>>>(x, 0, 1, pp, qp);   // profile slot
    deg_cnt_kernel<<<(EE + 255) / 256, 256>>>(ei, batch);
    scan1_kernel<<<nb, 256>>>();
    scan2_kernel<<<1, 512>>>(nb);
    scan3_kernel<<<nb, 256>>>();
    place_kernel<<<(EE + 255) / 256, 256>>>(ei);

    gather_kernel<<<NN / 8, 256>>>(pp, qp, bl1, h1p);
    gemm_bf16x3_kernel<<<gemm_blocks, 128, GEMM_SMEM>>>(h1p, 2, 3, pp, qp);
    foldW_kernel<<<1, 128>>>(Wl3, Wr3, bl3, Wlin, blin);
    gather2z_kernel<<<NN / 8, 256>>>(pp, qp, bl2);
    pool3_kernel<<<nb, 256>>>(batch);
    finalize_kernel<<<1, 128>>>(out);
}